// round 14
// baseline (speedup 1.0000x reference)
#include <cuda_runtime.h>
#include <math.h>
#include <stdint.h>

// ---------------- problem constants ----------------
#define BB 2
#define TT 2048
#define DD 1024
#define HH 16
#define HD 64
#define FF 4096
#define ROWS (BB * TT)          // 4096
#define LN_EPS 1e-5f
#define QKVN (3 * DD)           // 3072

// ---------------- scratch (__device__ globals; no allocation) ----------------
__device__ float g_h[ROWS * DD];
__device__ float g_qkv[ROWS * QKVN];        // fused Q|K|V, row stride 3072
__device__ float g_vt[BB * HH * HD * TT];   // [b,h][d][t]
__device__ float g_attn[ROWS * DD];
__device__ float g_xmid[ROWS * DD];
__device__ float g_h2[ROWS * DD];
__device__ float g_ff[ROWS * FF];
__device__ unsigned long long g_mask_bits[TT * (TT / 64)];
__device__ float g_wqkvt[QKVN * DD];
__device__ float g_wot[DD * DD];
__device__ float g_w1t[FF * DD];
__device__ float g_w2t[DD * FF];

// ---------------- helpers ----------------
__device__ __forceinline__ uint32_t f2tf32(float f) {
    uint32_t r;
    asm("cvt.rna.tf32.f32 %0, %1;" : "=r"(r) : "f"(f));
    return r;
}
__device__ __forceinline__ float gelu_exact(float x) {
    return 0.5f * x * (1.0f + erff(x * 0.70710678118654752f));
}
__device__ __forceinline__ void mma_tf32(float c[4], uint32_t a0, uint32_t a1,
                                         uint32_t a2, uint32_t a3,
                                         uint32_t b0, uint32_t b1) {
    asm volatile(
        "mma.sync.aligned.m16n8k8.row.col.f32.tf32.tf32.f32 "
        "{%0,%1,%2,%3}, {%4,%5,%6,%7}, {%8,%9}, {%0,%1,%2,%3};"
        : "+f"(c[0]), "+f"(c[1]), "+f"(c[2]), "+f"(c[3])
        : "r"(a0), "r"(a1), "r"(a2), "r"(a3), "r"(b0), "r"(b1));
}
__device__ __forceinline__ void ldsm_x4(uint32_t& r0, uint32_t& r1,
                                        uint32_t& r2, uint32_t& r3, uint32_t addr) {
    asm volatile("ldmatrix.sync.aligned.m8n8.x4.shared.b16 {%0,%1,%2,%3}, [%4];"
                 : "=r"(r0), "=r"(r1), "=r"(r2), "=r"(r3) : "r"(addr));
}
__device__ __forceinline__ void cp_async16(uint32_t saddr, const float* gaddr) {
    asm volatile("cp.async.cg.shared.global [%0], [%1], 16;" :: "r"(saddr), "l"(gaddr));
}
#define CP_COMMIT() asm volatile("cp.async.commit_group;" ::: "memory")
#define CP_WAIT1() asm volatile("cp.async.wait_group 1;" ::: "memory")
#define CP_WAIT0() asm volatile("cp.async.wait_group 0;" ::: "memory")
__device__ __forceinline__ void sts64(uint32_t addr, float a, float b) {
    asm volatile("st.shared.v2.f32 [%0], {%1,%2};" :: "r"(addr), "f"(a), "f"(b));
}

// ---------------- fused prepass: LN1 + 6 weight transposes + mask bits ----------------
#define PRE_BLOCKS 16640

__device__ __forceinline__ void tr_tile(const float* __restrict__ src,
                                        float* __restrict__ dst,
                                        int R, int C, int bx, int by,
                                        float (*t)[33])
{
    int c0 = bx * 32, r0 = by * 32;
    int tx = threadIdx.x & 31, ty = threadIdx.x >> 5;
#pragma unroll
    for (int i = 0; i < 32; i += 8)
        t[ty + i][tx] = src[(size_t)(r0 + ty + i) * C + c0 + tx];
    __syncthreads();
#pragma unroll
    for (int i = 0; i < 32; i += 8)
        dst[(size_t)(c0 + ty + i) * R + r0 + tx] = __uint_as_float(f2tf32(t[tx][ty + i]));
}

__device__ __forceinline__ void ln_row(const float* __restrict__ x,
                                       const float* __restrict__ gam,
                                       const float* __restrict__ bet,
                                       float* __restrict__ out, int row,
                                       float* red)
{
    int t = threadIdx.x;
    const float* xr = x + (size_t)row * DD;
    float4 xv = *(const float4*)(xr + t * 4);
    float s = xv.x + xv.y + xv.z + xv.w;
#pragma unroll
    for (int o = 16; o; o >>= 1) s += __shfl_xor_sync(0xffffffffu, s, o);
    if ((t & 31) == 0) red[t >> 5] = s;
    __syncthreads();
    float mu = 0.f;
#pragma unroll
    for (int i = 0; i < 8; i++) mu += red[i];
    mu *= (1.0f / (float)DD);
    __syncthreads();
    float dx = xv.x - mu, dy = xv.y - mu, dz = xv.z - mu, dw = xv.w - mu;
    float s2 = dx * dx + dy * dy + dz * dz + dw * dw;
#pragma unroll
    for (int o = 16; o; o >>= 1) s2 += __shfl_xor_sync(0xffffffffu, s2, o);
    if ((t & 31) == 0) red[t >> 5] = s2;
    __syncthreads();
    float var = 0.f;
#pragma unroll
    for (int i = 0; i < 8; i++) var += red[i];
    var *= (1.0f / (float)DD);
    float inv = rsqrtf(var + LN_EPS);
    float4 gv = *(const float4*)(gam + t * 4);
    float4 bv = *(const float4*)(bet + t * 4);
    float4 o4;
    o4.x = dx * inv * gv.x + bv.x;
    o4.y = dy * inv * gv.y + bv.y;
    o4.z = dz * inv * gv.z + bv.z;
    o4.w = dw * inv * gv.w + bv.w;
    *(float4*)(out + (size_t)row * DD + t * 4) = o4;
}

__global__ __launch_bounds__(256) void prepass_kernel(
    const float* __restrict__ x,
    const float* __restrict__ ln1_g, const float* __restrict__ ln1_b,
    const float* __restrict__ Wq, const float* __restrict__ Wk,
    const float* __restrict__ Wv, const float* __restrict__ Wo,
    const float* __restrict__ W1, const float* __restrict__ W2,
    const unsigned char* __restrict__ mask_raw)
{
    __shared__ float sh[32][33];
    int bid = blockIdx.x;

    if (bid < 4096) {                       // LN1
        ln_row(x, ln1_g, ln1_b, g_h, bid, &sh[0][0]);
        return;
    }
    bid -= 4096;
    if (bid < 4096) {                       // Wq/Wk/Wv -> wqkvt, Wo -> wot
        int z = bid >> 10, tile = bid & 1023;
        const float* src = (z == 0) ? Wq : (z == 1) ? Wk : (z == 2) ? Wv : Wo;
        float* dst = (z < 3) ? (g_wqkvt + (size_t)z * DD * DD) : g_wot;
        tr_tile(src, dst, DD, DD, tile & 31, tile >> 5, sh);
        return;
    }
    bid -= 4096;
    if (bid < 4096) {                       // W1 (1024x4096) -> w1t
        tr_tile(W1, g_w1t, DD, FF, bid & 127, bid >> 7, sh);
        return;
    }
    bid -= 4096;
    if (bid < 4096) {                       // W2 (4096x1024) -> w2t
        tr_tile(W2, g_w2t, FF, DD, bid & 31, bid >> 5, sh);
        return;
    }
    bid -= 4096;
    {                                       // mask bits
        int i = bid * 256 + threadIdx.x;
        int row = i >> 5, w = i & 31;
        bool one_byte = (mask_raw[2048] != 0);
        unsigned long long bits = 0ull;
        if (one_byte) {
            const unsigned char* p = mask_raw + (size_t)row * TT + w * 64;
#pragma unroll 8
            for (int j = 0; j < 64; j++) if (p[j]) bits |= 1ull << j;
        } else {
            const unsigned int* p = (const unsigned int*)mask_raw + (size_t)row * TT + w * 64;
#pragma unroll 8
            for (int j = 0; j < 64; j++) if (p[j]) bits |= 1ull << j;
        }
        g_mask_bits[i] = bits;
    }
}

// ---------------- V transpose per head ----------------
__global__ __launch_bounds__(256) void vtrans_kernel(const float* __restrict__ qkv,
                                                     float* __restrict__ vt)
{
    __shared__ float tsh[32][33];
    int bh = blockIdx.z;
    int b = bh >> 4, h = bh & 15;
    int t0 = blockIdx.x * 32, d0 = blockIdx.y * 32;
    int tx = threadIdx.x & 31, ty = threadIdx.x >> 5;
    const float* src = qkv + (size_t)b * TT * QKVN + 2048 + (size_t)h * HD;
#pragma unroll
    for (int i = 0; i < 32; i += 8)
        tsh[ty + i][tx] = src[(size_t)(t0 + ty + i) * QKVN + d0 + tx];
    __syncthreads();
    float* dst = vt + ((size_t)bh * HD + d0) * TT + t0;
#pragma unroll
    for (int i = 0; i < 32; i += 8)
        dst[(size_t)(ty + i) * TT + tx] = tsh[tx][ty + i];
}

// ---------------- LayerNorm (standalone, for LN2) ----------------
__global__ __launch_bounds__(256) void ln_kernel(const float* __restrict__ x,
                                                 const float* __restrict__ gam,
                                                 const float* __restrict__ bet,
                                                 float* __restrict__ out)
{
    __shared__ float red[8];
    ln_row(x, gam, bet, out, blockIdx.x, red);
}

// ---------------- tf32 mma.sync GEMM ----------------
#define GSTAGE 32768
#define GSMEM  (3 * GSTAGE)

template<int EPI>
__global__ __launch_bounds__(128, 2) void mma_gemm(
    const float* __restrict__ A, const float* __restrict__ Bt,
    const float* __restrict__ bias, const float* __restrict__ resid,
    float* __restrict__ C, int M, int N, int K)
{
    extern __shared__ unsigned char smem_raw[];
    const uint32_t sbase = (uint32_t)__cvta_generic_to_shared(smem_raw);
    const int tid = threadIdx.x;
    const int wid = tid >> 5, lane = tid & 31;
    const int wm = wid & 1, wn = wid >> 1;
    const int g = lane >> 2, t = lane & 3;
    const int mb = blockIdx.y, nb = blockIdx.x;

    const int rl = tid >> 3;
    const int ch = tid & 7;
    const uint32_t sw16 = (uint32_t)((ch ^ (rl & 7)) * 16);
    const float* Ag = A + (size_t)(mb * 128 + rl) * K + ch * 4;
    const float* Bg = Bt + (size_t)(nb * 128 + rl) * K + ch * 4;

    const int l7 = lane & 7, mat = lane >> 3;
    const uint32_t a_rp = (uint32_t)((l7 + (mat & 1) * 8) * 128);
    const int a_ca = mat >> 1;
    const uint32_t b_rp = (uint32_t)((l7 + (mat >> 1) * 8) * 128);
    const int b_ca = mat & 1;

    float acc[4][8][4];
#pragma unroll
    for (int i = 0; i < 4; i++)
#pragma unroll
        for (int j = 0; j < 8; j++)
#pragma unroll
            for (int r = 0; r < 4; r++) acc[i][j][r] = 0.f;

    const int NC = K / 32;

    auto issue = [&](int cc, int s) {
        const uint32_t ab = sbase + (uint32_t)s * GSTAGE;
        const size_t ko = (size_t)cc * 32;
#pragma unroll
        for (int p = 0; p < 8; p++) {
            uint32_t soff = (uint32_t)((p * 16 + rl) * 128) + sw16;
            cp_async16(ab + soff,          Ag + (size_t)(p * 16) * K + ko);
            cp_async16(ab + 16384u + soff, Bg + (size_t)(p * 16) * K + ko);
        }
        CP_COMMIT();
    };

    issue(0, 0);
    issue(1, 1);

    uint32_t af[2][4][4], bf[2][8][2];

    for (int c = 0; c < NC; c++) {
        if (c < NC - 1) { CP_WAIT1(); } else { CP_WAIT0(); }
        __syncthreads();
        if (c + 2 < NC) issue(c + 2, (c + 2) % 3);

        const uint32_t sa = sbase + (uint32_t)(c % 3) * GSTAGE;
        const uint32_t sb = sa + 16384u;

        auto load_frags = [&](int ks, uint32_t (*afd)[4], uint32_t (*bfd)[2]) {
            const int c0 = ks * 2;
#pragma unroll
            for (int mt = 0; mt < 4; mt++) {
                uint32_t addr = sa + (uint32_t)((wm * 64 + mt * 16) * 128) + a_rp
                              + (uint32_t)(((c0 + a_ca) ^ l7) * 16);
                ldsm_x4(afd[mt][0], afd[mt][1], afd[mt][2], afd[mt][3], addr);
            }
#pragma unroll
            for (int pr = 0; pr < 4; pr++) {
                uint32_t addr = sb + (uint32_t)((wn * 64 + pr * 16) * 128) + b_rp
                              + (uint32_t)(((c0 + b_ca) ^ l7) * 16);
                ldsm_x4(bfd[2 * pr][0], bfd[2 * pr][1], bfd[2 * pr + 1][0], bfd[2 * pr + 1][1], addr);
            }
        };

        load_frags(0, af[0], bf[0]);
#pragma unroll
        for (int ks = 0; ks < 4; ks++) {
            const int cur = ks & 1;
            if (ks < 3) load_frags(ks + 1, af[cur ^ 1], bf[cur ^ 1]);
#pragma unroll
            for (int mt = 0; mt < 4; mt++)
#pragma unroll
                for (int nt = 0; nt < 8; nt++)
                    mma_tf32(acc[mt][nt], af[cur][mt][0], af[cur][mt][1],
                             af[cur][mt][2], af[cur][mt][3],
                             bf[cur][nt][0], bf[cur][nt][1]);
        }
    }

#pragma unroll
    for (int mt = 0; mt < 4; mt++) {
        int row0 = mb * 128 + wm * 64 + mt * 16 + g;
#pragma unroll
        for (int nt = 0; nt < 8; nt++) {
            int col = nb * 128 + wn * 64 + nt * 8 + 2 * t;
#pragma unroll
            for (int half = 0; half < 2; half++) {
                int row = row0 + half * 8;
                float v0 = acc[mt][nt][half * 2 + 0];
                float v1 = acc[mt][nt][half * 2 + 1];
                if (EPI >= 1) { v0 += bias[col]; v1 += bias[col + 1]; }
                if (EPI == 3) { v0 = gelu_exact(v0); v1 = gelu_exact(v1); }
                if (EPI == 2) {
                    const float* rp = resid + (size_t)row * N + col;
                    v0 += rp[0]; v1 += rp[1];
                }
                float2 o2; o2.x = v0; o2.y = v1;
                *(float2*)(C + (size_t)row * N + col) = o2;
            }
        }
    }
}

// ---------------- tensor-core flash attention, q-tile 128, LPT block order ----------------
#define AQ_OFF 0
#define AK_OFF 32768
#define AV_OFF 65536
#define AP_OFF 98304
#define ATTN_SMEM 131072

__global__ __launch_bounds__(256, 1) void attn_kernel(
    const float* __restrict__ QKV, const float* __restrict__ Vt,
    const unsigned long long* __restrict__ mbits, float* __restrict__ O)
{
    extern __shared__ unsigned char sm_raw[];
    const uint32_t sb = (uint32_t)__cvta_generic_to_shared(sm_raw);
    const int tid = threadIdx.x;
    const int wid = tid >> 5, lane = tid & 31;
    const int l7 = lane & 7, mat = lane >> 3;
    const int g = lane >> 2, t = lane & 3;
    // LPT: heaviest q-tiles (largest qb) launch first
    const int qb = (int)gridDim.x - 1 - (int)blockIdx.x;
    const int h = blockIdx.y, b = blockIdx.z;
    const int q0 = qb * 128;

    const float* qg = QKV + (size_t)b * TT * QKVN + (size_t)h * HD;
    const float* kg = QKV + (size_t)b * TT * QKVN + 1024 + (size_t)h * HD;
    const float* vtg = Vt + (size_t)(b * HH + h) * HD * TT;

    const int crowQ = tid >> 1, chalfQ = (tid & 1) * 8;
    const uint32_t cswQ = (uint32_t)(crowQ & 7);
    const int crowK = tid >> 2, cqK = (tid & 3) * 4;
    const uint32_t cswK = (uint32_t)(crowK & 7);

    {
#pragma unroll
        for (int i = 0; i < 8; i++) {
            int cc = chalfQ + i;
            uint32_t sa = sb + AQ_OFF + (uint32_t)((cc >> 3) * 16384 + crowQ * 128)
                        + (uint32_t)((((uint32_t)(cc & 7)) ^ cswQ) * 16);
            cp_async16(sa, qg + (size_t)(q0 + crowQ) * QKVN + cc * 4);
        }
    }
    auto ld_k = [&](uint32_t dst, int tok0) {
#pragma unroll
        for (int i = 0; i < 4; i++) {
            int cc = cqK + i;
            uint32_t sa = dst + (uint32_t)((cc >> 3) * 8192 + crowK * 128)
                        + (uint32_t)((((uint32_t)(cc & 7)) ^ cswK) * 16);
            cp_async16(sa, kg + (size_t)(tok0 + crowK) * QKVN + cc * 4);
        }
    };
    auto ld_v = [&](uint32_t dst, int k0) {
#pragma unroll
        for (int i = 0; i < 4; i++) {
            int cc = cqK + i;
            uint32_t sa = dst + (uint32_t)((cc >> 3) * 8192 + crowK * 128)
                        + (uint32_t)((((uint32_t)(cc & 7)) ^ cswK) * 16);
            cp_async16(sa, vtg + (size_t)crowK * TT + k0 + cc * 4);
        }
    };

    ld_k(sb + AK_OFF, 0);
    ld_v(sb + AV_OFF, 0);
    CP_COMMIT();

    float m0 = -INFINITY, m1 = -INFINITY, le0 = 0.f, le1 = 0.f;
    float oacc[8][4];
#pragma unroll
    for (int j = 0; j < 8; j++)
#pragma unroll
        for (int r = 0; r < 4; r++) oacc[j][r] = 0.f;

    const uint32_t a_rp = (uint32_t)((wid * 16 + l7 + (mat & 1) * 8) * 128);
    const int a_ca = mat >> 1;
    const uint32_t b_rp = (uint32_t)((l7 + (mat >> 1) * 8) * 128);
    const int b_ca = mat & 1;
    const int rowq0 = q0 + wid * 16 + g;
    const int rmax = q0 + wid * 16 + 15;
    const int kmax = 2 * qb + 1;

    for (int kb = 0; kb <= kmax; kb++) {
        CP_WAIT0();
        __syncthreads();
        const int s = kb & 1;
        if (kb < kmax) {
            ld_k(sb + AK_OFF + (s ^ 1) * 16384, (kb + 1) * 64);
            ld_v(sb + AV_OFF + (s ^ 1) * 16384, (kb + 1) * 64);
            CP_COMMIT();
        }
        if (kb * 64 > rmax) continue;      // warp-uniform causal skip
        const uint32_t ksm = sb + AK_OFF + s * 16384;
        const uint32_t vsm = sb + AV_OFF + s * 16384;

        // prefetch mask words (gmem) before the S MMAs hide their latency
        unsigned long long w0 = mbits[(size_t)rowq0 * 32 + kb];
        unsigned long long w1 = mbits[(size_t)(rowq0 + 8) * 32 + kb];

        // ---- S = Q K^T ----
        float sacc[8][4];
#pragma unroll
        for (int j = 0; j < 8; j++)
#pragma unroll
            for (int r = 0; r < 4; r++) sacc[j][r] = 0.f;
#pragma unroll
        for (int ks = 0; ks < 8; ks++) {
            const int c0 = ks * 2;
            uint32_t a0, a1, a2, a3;
            {
                int cc = c0 + a_ca;
                uint32_t addr = sb + AQ_OFF + (uint32_t)((cc >> 3) * 16384) + a_rp
                              + (uint32_t)((((uint32_t)(cc & 7)) ^ (uint32_t)l7) * 16);
                ldsm_x4(a0, a1, a2, a3, addr);
            }
            uint32_t bf[8][2];
#pragma unroll
            for (int pr = 0; pr < 4; pr++) {
                int cc = c0 + b_ca;
                uint32_t addr = ksm + (uint32_t)((cc >> 3) * 8192) + (uint32_t)(pr * 16 * 128)
                              + b_rp + (uint32_t)((((uint32_t)(cc & 7)) ^ (uint32_t)l7) * 16);
                ldsm_x4(bf[2 * pr][0], bf[2 * pr][1], bf[2 * pr + 1][0], bf[2 * pr + 1][1], addr);
            }
#pragma unroll
            for (int nt = 0; nt < 8; nt++)
                mma_tf32(sacc[nt], a0, a1, a2, a3, bf[nt][0], bf[nt][1]);
        }

        // ---- mask + scale + online softmax ----
        float tm0 = -INFINITY, tm1 = -INFINITY;
#pragma unroll
        for (int nt = 0; nt < 8; nt++) {
            int col = nt * 8 + 2 * t;
            sacc[nt][0] = ((w0 >> col) & 1ull) ? sacc[nt][0] * 0.125f : -1e9f;
            sacc[nt][1] = ((w0 >> (col + 1)) & 1ull) ? sacc[nt][1] * 0.125f : -1e9f;
            sacc[nt][2] = ((w1 >> col) & 1ull) ? sacc[nt][2] * 0.125f : -1e9f;
            sacc[nt][3] = ((w1 >> (col + 1)) & 1ull) ? sacc[nt][3] * 0.125f : -1e9f;
            tm0 = fmaxf(tm0, fmaxf(sacc[nt][0], sacc[nt][1]));
            tm1 = fmaxf(tm1, fmaxf(sacc[nt][2], sacc[nt][3]));
        }
#pragma unroll
        for (int o = 1; o <= 2; o <<= 1) {
            tm0 = fmaxf(tm0, __shfl_xor_sync(0xffffffffu, tm0, o));
            tm1 = fmaxf(tm1, __shfl_xor_sync(0xffffffffu, tm1, o));
        }
        float mn0 = fmaxf(m0, tm0), mn1 = fmaxf(m1, tm1);
        float al0 = __expf(m0 - mn0), al1 = __expf(m1 - mn1);
        m0 = mn0; m1 = mn1;
        float rs0 = 0.f, rs1 = 0.f;
#pragma unroll
        for (int nt = 0; nt < 8; nt++) {
            float p0 = __expf(sacc[nt][0] - mn0);
            float p1 = __expf(sacc[nt][1] - mn0);
            float p2 = __expf(sacc[nt][2] - mn1);
            float p3 = __expf(sacc[nt][3] - mn1);
            rs0 += p0 + p1; rs1 += p2 + p3;
            int cp = nt * 8 + 2 * t;
            int cc = cp >> 2;
            uint32_t base = sb + AP_OFF + (uint32_t)((cc >> 3) * 16384)
                          + (uint32_t)((((uint32_t)(cc & 7)) ^ (uint32_t)g) * 16)
                          + (uint32_t)((cp & 3) * 4);
            sts64(base + (uint32_t)((wid * 16 + g) * 128), p0, p1);
            sts64(base + (uint32_t)((wid * 16 + g + 8) * 128), p2, p3);
        }
#pragma unroll
        for (int o = 1; o <= 2; o <<= 1) {
            rs0 += __shfl_xor_sync(0xffffffffu, rs0, o);
            rs1 += __shfl_xor_sync(0xffffffffu, rs1, o);
        }
        le0 = le0 * al0 + rs0;
        le1 = le1 * al1 + rs1;
#pragma unroll
        for (int nt = 0; nt < 8; nt++) {
            oacc[nt][0] *= al0; oacc[nt][1] *= al0;
            oacc[nt][2] *= al1; oacc[nt][3] *= al1;
        }
        __syncwarp(0xffffffffu);   // P rows are warp-private

        // ---- O += P V ----
#pragma unroll
        for (int ks = 0; ks < 8; ks++) {
            const int c0 = ks * 2;
            uint32_t a0, a1, a2, a3;
            {
                int cc = c0 + a_ca;
                uint32_t addr = sb + AP_OFF + (uint32_t)((cc >> 3) * 16384) + a_rp
                              + (uint32_t)((((uint32_t)(cc & 7)) ^ (uint32_t)l7) * 16);
                ldsm_x4(a0, a1, a2, a3, addr);
            }
            uint32_t bf[8][2];
#pragma unroll
            for (int pr = 0; pr < 4; pr++) {
                int cc = c0 + b_ca;
                uint32_t addr = vsm + (uint32_t)((cc >> 3) * 8192) + (uint32_t)(pr * 16 * 128)
                              + b_rp + (uint32_t)((((uint32_t)(cc & 7)) ^ (uint32_t)l7) * 16);
                ldsm_x4(bf[2 * pr][0], bf[2 * pr][1], bf[2 * pr + 1][0], bf[2 * pr + 1][1], addr);
            }
#pragma unroll
            for (int nt = 0; nt < 8; nt++)
                mma_tf32(oacc[nt], a0, a1, a2, a3, bf[nt][0], bf[nt][1]);
        }
    }

    // ---- normalize + write ----
    float inv0 = 1.0f / le0, inv1 = 1.0f / le1;
    float* ob = O + (size_t)b * TT * DD + (size_t)h * HD;
#pragma unroll
    for (int nt = 0; nt < 8; nt++) {
        int col = nt * 8 + 2 * t;
        float2 o2;
        o2.x = oacc[nt][0] * inv0; o2.y = oacc[nt][1] * inv0;
        *(float2*)(ob + (size_t)rowq0 * DD + col) = o2;
        o2.x = oacc[nt][2] * inv1; o2.y = oacc[nt][3] * inv1;
        *(float2*)(ob + (size_t)(rowq0 + 8) * DD + col) = o2;
    }
}

// ---------------- launch ----------------
extern "C" void kernel_launch(void* const* d_in, const int* in_sizes, int n_in,
                              void* d_out, int out_size)
{
    (void)in_sizes; (void)n_in; (void)out_size;
    const float* x     = (const float*)d_in[0];
    const unsigned char* mask_raw = (const unsigned char*)d_in[1];
    const float* ln1_g = (const float*)d_in[2];
    const float* ln1_b = (const float*)d_in[3];
    const float* ln2_g = (const float*)d_in[4];
    const float* ln2_b = (const float*)d_in[5];
    const float* Wq    = (const float*)d_in[6];
    const float* Wk    = (const float*)d_in[7];
    const float* Wv    = (const float*)d_in[8];
    const float* Wo    = (const float*)d_in[9];
    const float* bo    = (const float*)d_in[10];
    const float* W1    = (const float*)d_in[11];
    const float* b1    = (const float*)d_in[12];
    const float* W2    = (const float*)d_in[13];
    const float* b2    = (const float*)d_in[14];
    float* out = (float*)d_out;

    float *h, *qkv, *vt, *attn, *xmid, *h2, *ff;
    float *wqkvt, *wot, *w1t, *w2t;
    unsigned long long* mbits;
    cudaGetSymbolAddress((void**)&h,     g_h);
    cudaGetSymbolAddress((void**)&qkv,   g_qkv);
    cudaGetSymbolAddress((void**)&vt,    g_vt);
    cudaGetSymbolAddress((void**)&attn,  g_attn);
    cudaGetSymbolAddress((void**)&xmid,  g_xmid);
    cudaGetSymbolAddress((void**)&h2,    g_h2);
    cudaGetSymbolAddress((void**)&ff,    g_ff);
    cudaGetSymbolAddress((void**)&wqkvt, g_wqkvt);
    cudaGetSymbolAddress((void**)&wot,   g_wot);
    cudaGetSymbolAddress((void**)&w1t,   g_w1t);
    cudaGetSymbolAddress((void**)&w2t,   g_w2t);
    cudaGetSymbolAddress((void**)&mbits, g_mask_bits);

    cudaFuncSetAttribute(attn_kernel, cudaFuncAttributeMaxDynamicSharedMemorySize, ATTN_SMEM);
    cudaFuncSetAttribute(mma_gemm<0>, cudaFuncAttributeMaxDynamicSharedMemorySize, GSMEM);
    cudaFuncSetAttribute(mma_gemm<2>, cudaFuncAttributeMaxDynamicSharedMemorySize, GSMEM);
    cudaFuncSetAttribute(mma_gemm<3>, cudaFuncAttributeMaxDynamicSharedMemorySize, GSMEM);

    // 0) fused prepass: LN1 + all weight transposes + mask bits (one launch)
    prepass_kernel<<<PRE_BLOCKS, 256>>>(x, ln1_g, ln1_b, Wq, Wk, Wv, Wo, W1, W2, mask_raw);
    // 1) fused QKV projection
    mma_gemm<0><<<dim3(QKVN / 128, ROWS / 128), 128, GSMEM>>>(h, wqkvt, nullptr, nullptr, qkv, ROWS, QKVN, DD);
    // 1b) V transpose per head
    vtrans_kernel<<<dim3(TT / 32, HD / 32, BB * HH), 256>>>(qkv, vt);
    // 2) attention (tensor core, 128-row q-tiles, LPT order)
    attn_kernel<<<dim3(TT / 128, HH, BB), 256, ATTN_SMEM>>>(qkv, vt, mbits, attn);
    // 3) Wo + bias + residual(x)
    dim3 g1024(DD / 128, ROWS / 128);
    mma_gemm<2><<<g1024, 128, GSMEM>>>(attn, wot, bo, x, xmid, ROWS, DD, DD);
    // 4) LN2
    ln_kernel<<<ROWS, 256>>>(xmid, ln2_g, ln2_b, h2);
    // 5) FFN up + GELU
    mma_gemm<3><<<dim3(FF / 128, ROWS / 128), 128, GSMEM>>>(h2, w1t, b1, nullptr, ff, ROWS, FF, DD);
    // 6) FFN down + bias + residual(xmid) -> out
    mma_gemm<2><<<g1024, 128, GSMEM>>>(ff, w2t, b2, xmid, out, ROWS, DD, FF);
}

// round 17
// speedup vs baseline: 1.0361x; 1.0361x over previous
#include <cuda_runtime.h>
#include <math.h>
#include <stdint.h>

// ---------------- problem constants ----------------
#define BB 2
#define TT 2048
#define DD 1024
#define HH 16
#define HD 64
#define FF 4096
#define ROWS (BB * TT)          // 4096
#define LN_EPS 1e-5f
#define QKVN (3 * DD)           // 3072

// ---------------- scratch (__device__ globals; no allocation) ----------------
__device__ float g_h[ROWS * DD];
__device__ float g_qkv[ROWS * QKVN];        // fused Q|K|V, row stride 3072
__device__ float g_vt[BB * HH * HD * TT];   // [b,h][d][t]
__device__ float g_attn[ROWS * DD];
__device__ float g_xmid[ROWS * DD];
__device__ float g_h2[ROWS * DD];
__device__ float g_ff[ROWS * FF];
__device__ unsigned long long g_mask_bits[TT * (TT / 64)];
__device__ float g_wqkvt[QKVN * DD];
__device__ float g_wot[DD * DD];
__device__ float g_w1t[FF * DD];
__device__ float g_w2t[DD * FF];

// ---------------- helpers ----------------
__device__ __forceinline__ uint32_t f2tf32(float f) {
    uint32_t r;
    asm("cvt.rna.tf32.f32 %0, %1;" : "=r"(r) : "f"(f));
    return r;
}
__device__ __forceinline__ float gelu_exact(float x) {
    return 0.5f * x * (1.0f + erff(x * 0.70710678118654752f));
}
__device__ __forceinline__ void mma_tf32(float c[4], uint32_t a0, uint32_t a1,
                                         uint32_t a2, uint32_t a3,
                                         uint32_t b0, uint32_t b1) {
    asm volatile(
        "mma.sync.aligned.m16n8k8.row.col.f32.tf32.tf32.f32 "
        "{%0,%1,%2,%3}, {%4,%5,%6,%7}, {%8,%9}, {%0,%1,%2,%3};"
        : "+f"(c[0]), "+f"(c[1]), "+f"(c[2]), "+f"(c[3])
        : "r"(a0), "r"(a1), "r"(a2), "r"(a3), "r"(b0), "r"(b1));
}
__device__ __forceinline__ void ldsm_x4(uint32_t& r0, uint32_t& r1,
                                        uint32_t& r2, uint32_t& r3, uint32_t addr) {
    asm volatile("ldmatrix.sync.aligned.m8n8.x4.shared.b16 {%0,%1,%2,%3}, [%4];"
                 : "=r"(r0), "=r"(r1), "=r"(r2), "=r"(r3) : "r"(addr));
}
__device__ __forceinline__ void cp_async16(uint32_t saddr, const float* gaddr) {
    asm volatile("cp.async.cg.shared.global [%0], [%1], 16;" :: "r"(saddr), "l"(gaddr));
}
#define CP_COMMIT() asm volatile("cp.async.commit_group;" ::: "memory")
#define CP_WAIT1() asm volatile("cp.async.wait_group 1;" ::: "memory")
#define CP_WAIT0() asm volatile("cp.async.wait_group 0;" ::: "memory")
__device__ __forceinline__ void sts64(uint32_t addr, float a, float b) {
    asm volatile("st.shared.v2.f32 [%0], {%1,%2};" :: "r"(addr), "f"(a), "f"(b));
}

// ---------------- fused prepass: LN1 + 6 weight transposes + mask bits ----------------
#define PRE_BLOCKS 16640

__device__ __forceinline__ void tr_tile(const float* __restrict__ src,
                                        float* __restrict__ dst,
                                        int R, int C, int bx, int by,
                                        float (*t)[33])
{
    int c0 = bx * 32, r0 = by * 32;
    int tx = threadIdx.x & 31, ty = threadIdx.x >> 5;
#pragma unroll
    for (int i = 0; i < 32; i += 8)
        t[ty + i][tx] = src[(size_t)(r0 + ty + i) * C + c0 + tx];
    __syncthreads();
#pragma unroll
    for (int i = 0; i < 32; i += 8)
        dst[(size_t)(c0 + ty + i) * R + r0 + tx] = __uint_as_float(f2tf32(t[tx][ty + i]));
}

__device__ __forceinline__ void ln_row(const float* __restrict__ x,
                                       const float* __restrict__ gam,
                                       const float* __restrict__ bet,
                                       float* __restrict__ out, int row,
                                       float* red)
{
    int t = threadIdx.x;
    const float* xr = x + (size_t)row * DD;
    float4 xv = *(const float4*)(xr + t * 4);
    float s = xv.x + xv.y + xv.z + xv.w;
#pragma unroll
    for (int o = 16; o; o >>= 1) s += __shfl_xor_sync(0xffffffffu, s, o);
    if ((t & 31) == 0) red[t >> 5] = s;
    __syncthreads();
    float mu = 0.f;
#pragma unroll
    for (int i = 0; i < 8; i++) mu += red[i];
    mu *= (1.0f / (float)DD);
    __syncthreads();
    float dx = xv.x - mu, dy = xv.y - mu, dz = xv.z - mu, dw = xv.w - mu;
    float s2 = dx * dx + dy * dy + dz * dz + dw * dw;
#pragma unroll
    for (int o = 16; o; o >>= 1) s2 += __shfl_xor_sync(0xffffffffu, s2, o);
    if ((t & 31) == 0) red[t >> 5] = s2;
    __syncthreads();
    float var = 0.f;
#pragma unroll
    for (int i = 0; i < 8; i++) var += red[i];
    var *= (1.0f / (float)DD);
    float inv = rsqrtf(var + LN_EPS);
    float4 gv = *(const float4*)(gam + t * 4);
    float4 bv = *(const float4*)(bet + t * 4);
    float4 o4;
    o4.x = dx * inv * gv.x + bv.x;
    o4.y = dy * inv * gv.y + bv.y;
    o4.z = dz * inv * gv.z + bv.z;
    o4.w = dw * inv * gv.w + bv.w;
    *(float4*)(out + (size_t)row * DD + t * 4) = o4;
}

__global__ __launch_bounds__(256) void prepass_kernel(
    const float* __restrict__ x,
    const float* __restrict__ ln1_g, const float* __restrict__ ln1_b,
    const float* __restrict__ Wq, const float* __restrict__ Wk,
    const float* __restrict__ Wv, const float* __restrict__ Wo,
    const float* __restrict__ W1, const float* __restrict__ W2,
    const unsigned char* __restrict__ mask_raw)
{
    __shared__ float sh[32][33];
    int bid = blockIdx.x;

    if (bid < 4096) {                       // LN1
        ln_row(x, ln1_g, ln1_b, g_h, bid, &sh[0][0]);
        return;
    }
    bid -= 4096;
    if (bid < 4096) {                       // Wq/Wk/Wv -> wqkvt, Wo -> wot
        int z = bid >> 10, tile = bid & 1023;
        const float* src = (z == 0) ? Wq : (z == 1) ? Wk : (z == 2) ? Wv : Wo;
        float* dst = (z < 3) ? (g_wqkvt + (size_t)z * DD * DD) : g_wot;
        tr_tile(src, dst, DD, DD, tile & 31, tile >> 5, sh);
        return;
    }
    bid -= 4096;
    if (bid < 4096) {                       // W1 (1024x4096) -> w1t
        tr_tile(W1, g_w1t, DD, FF, bid & 127, bid >> 7, sh);
        return;
    }
    bid -= 4096;
    if (bid < 4096) {                       // W2 (4096x1024) -> w2t
        tr_tile(W2, g_w2t, FF, DD, bid & 31, bid >> 5, sh);
        return;
    }
    bid -= 4096;
    {                                       // mask bits
        int i = bid * 256 + threadIdx.x;
        int row = i >> 5, w = i & 31;
        bool one_byte = (mask_raw[2048] != 0);
        unsigned long long bits = 0ull;
        if (one_byte) {
            const unsigned char* p = mask_raw + (size_t)row * TT + w * 64;
#pragma unroll 8
            for (int j = 0; j < 64; j++) if (p[j]) bits |= 1ull << j;
        } else {
            const unsigned int* p = (const unsigned int*)mask_raw + (size_t)row * TT + w * 64;
#pragma unroll 8
            for (int j = 0; j < 64; j++) if (p[j]) bits |= 1ull << j;
        }
        g_mask_bits[i] = bits;
    }
}

// ---------------- V transpose per head ----------------
__global__ __launch_bounds__(256) void vtrans_kernel(const float* __restrict__ qkv,
                                                     float* __restrict__ vt)
{
    __shared__ float tsh[32][33];
    int bh = blockIdx.z;
    int b = bh >> 4, h = bh & 15;
    int t0 = blockIdx.x * 32, d0 = blockIdx.y * 32;
    int tx = threadIdx.x & 31, ty = threadIdx.x >> 5;
    const float* src = qkv + (size_t)b * TT * QKVN + 2048 + (size_t)h * HD;
#pragma unroll
    for (int i = 0; i < 32; i += 8)
        tsh[ty + i][tx] = src[(size_t)(t0 + ty + i) * QKVN + d0 + tx];
    __syncthreads();
    float* dst = vt + ((size_t)bh * HD + d0) * TT + t0;
#pragma unroll
    for (int i = 0; i < 32; i += 8)
        dst[(size_t)(ty + i) * TT + tx] = tsh[tx][ty + i];
}

// ---------------- LayerNorm (standalone, for LN2) ----------------
__global__ __launch_bounds__(256) void ln_kernel(const float* __restrict__ x,
                                                 const float* __restrict__ gam,
                                                 const float* __restrict__ bet,
                                                 float* __restrict__ out)
{
    __shared__ float red[8];
    ln_row(x, gam, bet, out, blockIdx.x, red);
}

// ---------------- tf32 mma.sync GEMM ----------------
#define GSTAGE 32768
#define GSMEM  (3 * GSTAGE)

template<int EPI>
__global__ __launch_bounds__(128, 2) void mma_gemm(
    const float* __restrict__ A, const float* __restrict__ Bt,
    const float* __restrict__ bias, const float* __restrict__ resid,
    float* __restrict__ C, int M, int N, int K)
{
    extern __shared__ unsigned char smem_raw[];
    const uint32_t sbase = (uint32_t)__cvta_generic_to_shared(smem_raw);
    const int tid = threadIdx.x;
    const int wid = tid >> 5, lane = tid & 31;
    const int wm = wid & 1, wn = wid >> 1;
    const int g = lane >> 2, t = lane & 3;
    const int mb = blockIdx.y, nb = blockIdx.x;

    const int rl = tid >> 3;
    const int ch = tid & 7;
    const uint32_t sw16 = (uint32_t)((ch ^ (rl & 7)) * 16);
    const float* Ag = A + (size_t)(mb * 128 + rl) * K + ch * 4;
    const float* Bg = Bt + (size_t)(nb * 128 + rl) * K + ch * 4;

    const int l7 = lane & 7, mat = lane >> 3;
    const uint32_t a_rp = (uint32_t)((l7 + (mat & 1) * 8) * 128);
    const int a_ca = mat >> 1;
    const uint32_t b_rp = (uint32_t)((l7 + (mat >> 1) * 8) * 128);
    const int b_ca = mat & 1;

    float acc[4][8][4];
#pragma unroll
    for (int i = 0; i < 4; i++)
#pragma unroll
        for (int j = 0; j < 8; j++)
#pragma unroll
            for (int r = 0; r < 4; r++) acc[i][j][r] = 0.f;

    const int NC = K / 32;

    auto issue = [&](int cc, int s) {
        const uint32_t ab = sbase + (uint32_t)s * GSTAGE;
        const size_t ko = (size_t)cc * 32;
#pragma unroll
        for (int p = 0; p < 8; p++) {
            uint32_t soff = (uint32_t)((p * 16 + rl) * 128) + sw16;
            cp_async16(ab + soff,          Ag + (size_t)(p * 16) * K + ko);
            cp_async16(ab + 16384u + soff, Bg + (size_t)(p * 16) * K + ko);
        }
        CP_COMMIT();
    };

    issue(0, 0);
    issue(1, 1);

    uint32_t af[2][4][4], bf[2][8][2];

    for (int c = 0; c < NC; c++) {
        if (c < NC - 1) { CP_WAIT1(); } else { CP_WAIT0(); }
        __syncthreads();
        if (c + 2 < NC) issue(c + 2, (c + 2) % 3);

        const uint32_t sa = sbase + (uint32_t)(c % 3) * GSTAGE;
        const uint32_t sb = sa + 16384u;

        auto load_frags = [&](int ks, uint32_t (*afd)[4], uint32_t (*bfd)[2]) {
            const int c0 = ks * 2;
#pragma unroll
            for (int mt = 0; mt < 4; mt++) {
                uint32_t addr = sa + (uint32_t)((wm * 64 + mt * 16) * 128) + a_rp
                              + (uint32_t)(((c0 + a_ca) ^ l7) * 16);
                ldsm_x4(afd[mt][0], afd[mt][1], afd[mt][2], afd[mt][3], addr);
            }
#pragma unroll
            for (int pr = 0; pr < 4; pr++) {
                uint32_t addr = sb + (uint32_t)((wn * 64 + pr * 16) * 128) + b_rp
                              + (uint32_t)(((c0 + b_ca) ^ l7) * 16);
                ldsm_x4(bfd[2 * pr][0], bfd[2 * pr][1], bfd[2 * pr + 1][0], bfd[2 * pr + 1][1], addr);
            }
        };

        load_frags(0, af[0], bf[0]);
#pragma unroll
        for (int ks = 0; ks < 4; ks++) {
            const int cur = ks & 1;
            if (ks < 3) load_frags(ks + 1, af[cur ^ 1], bf[cur ^ 1]);
#pragma unroll
            for (int mt = 0; mt < 4; mt++)
#pragma unroll
                for (int nt = 0; nt < 8; nt++)
                    mma_tf32(acc[mt][nt], af[cur][mt][0], af[cur][mt][1],
                             af[cur][mt][2], af[cur][mt][3],
                             bf[cur][nt][0], bf[cur][nt][1]);
        }
    }

#pragma unroll
    for (int mt = 0; mt < 4; mt++) {
        int row0 = mb * 128 + wm * 64 + mt * 16 + g;
#pragma unroll
        for (int nt = 0; nt < 8; nt++) {
            int col = nb * 128 + wn * 64 + nt * 8 + 2 * t;
#pragma unroll
            for (int half = 0; half < 2; half++) {
                int row = row0 + half * 8;
                float v0 = acc[mt][nt][half * 2 + 0];
                float v1 = acc[mt][nt][half * 2 + 1];
                if (EPI >= 1) { v0 += bias[col]; v1 += bias[col + 1]; }
                if (EPI == 3) { v0 = gelu_exact(v0); v1 = gelu_exact(v1); }
                if (EPI == 2) {
                    const float* rp = resid + (size_t)row * N + col;
                    v0 += rp[0]; v1 += rp[1];
                }
                float2 o2; o2.x = v0; o2.y = v1;
                *(float2*)(C + (size_t)row * N + col) = o2;
            }
        }
    }
}

// ---------------- tensor-core flash attention, q-tile 128, sparsity-gated ----------------
#define AQ_OFF 0
#define AK_OFF 32768
#define AV_OFF 65536
#define AP_OFF 98304
#define ATTN_SMEM 131072

__global__ __launch_bounds__(256, 1) void attn_kernel(
    const float* __restrict__ QKV, const float* __restrict__ Vt,
    const unsigned long long* __restrict__ mbits, float* __restrict__ O)
{
    extern __shared__ unsigned char sm_raw[];
    const uint32_t sb = (uint32_t)__cvta_generic_to_shared(sm_raw);
    const int tid = threadIdx.x;
    const int wid = tid >> 5, lane = tid & 31;
    const int l7 = lane & 7, mat = lane >> 3;
    const int g = lane >> 2, t = lane & 3;
    // LPT: heaviest q-tiles (largest qb) launch first
    const int qb = (int)gridDim.x - 1 - (int)blockIdx.x;
    const int h = blockIdx.y, b = blockIdx.z;
    const int q0 = qb * 128;

    const float* qg = QKV + (size_t)b * TT * QKVN + (size_t)h * HD;
    const float* kg = QKV + (size_t)b * TT * QKVN + 1024 + (size_t)h * HD;
    const float* vtg = Vt + (size_t)(b * HH + h) * HD * TT;

    const int crowQ = tid >> 1, chalfQ = (tid & 1) * 8;
    const uint32_t cswQ = (uint32_t)(crowQ & 7);
    const int crowK = tid >> 2, cqK = (tid & 3) * 4;
    const uint32_t cswK = (uint32_t)(crowK & 7);

    {
#pragma unroll
        for (int i = 0; i < 8; i++) {
            int cc = chalfQ + i;
            uint32_t sa = sb + AQ_OFF + (uint32_t)((cc >> 3) * 16384 + crowQ * 128)
                        + (uint32_t)((((uint32_t)(cc & 7)) ^ cswQ) * 16);
            cp_async16(sa, qg + (size_t)(q0 + crowQ) * QKVN + cc * 4);
        }
    }
    auto ld_k = [&](uint32_t dst, int tok0) {
#pragma unroll
        for (int i = 0; i < 4; i++) {
            int cc = cqK + i;
            uint32_t sa = dst + (uint32_t)((cc >> 3) * 8192 + crowK * 128)
                        + (uint32_t)((((uint32_t)(cc & 7)) ^ cswK) * 16);
            cp_async16(sa, kg + (size_t)(tok0 + crowK) * QKVN + cc * 4);
        }
    };
    auto ld_v = [&](uint32_t dst, int k0) {
#pragma unroll
        for (int i = 0; i < 4; i++) {
            int cc = cqK + i;
            uint32_t sa = dst + (uint32_t)((cc >> 3) * 8192 + crowK * 128)
                        + (uint32_t)((((uint32_t)(cc & 7)) ^ cswK) * 16);
            cp_async16(sa, vtg + (size_t)crowK * TT + k0 + cc * 4);
        }
    };

    ld_k(sb + AK_OFF, 0);
    ld_v(sb + AV_OFF, 0);
    CP_COMMIT();

    float m0 = -INFINITY, m1 = -INFINITY, le0 = 0.f, le1 = 0.f;
    float oacc[8][4];
#pragma unroll
    for (int j = 0; j < 8; j++)
#pragma unroll
        for (int r = 0; r < 4; r++) oacc[j][r] = 0.f;

    const uint32_t a_rp = (uint32_t)((wid * 16 + l7 + (mat & 1) * 8) * 128);
    const int a_ca = mat >> 1;
    const uint32_t b_rp = (uint32_t)((l7 + (mat >> 1) * 8) * 128);
    const int b_ca = mat & 1;
    const int rowq0 = q0 + wid * 16 + g;
    const int kmax = 2 * qb + 1;

    for (int kb = 0; kb <= kmax; kb++) {
        CP_WAIT0();
        __syncthreads();
        const int s = kb & 1;
        if (kb < kmax) {
            ld_k(sb + AK_OFF + (s ^ 1) * 16384, (kb + 1) * 64);
            ld_v(sb + AV_OFF + (s ^ 1) * 16384, (kb + 1) * 64);
            CP_COMMIT();
        }

        // mask words for this tile (this thread's 2 rows)
        unsigned long long w0 = mbits[(size_t)rowq0 * 32 + kb];
        unsigned long long w1 = mbits[(size_t)(rowq0 + 8) * 32 + kb];
        // warp-wide group occupancy (8 groups of 8 columns); warp-uniform
        unsigned long long cw = w0 | w1;
        unsigned lo = __reduce_or_sync(0xffffffffu, (unsigned)cw);
        unsigned hi = __reduce_or_sync(0xffffffffu, (unsigned)(cw >> 32));
        unsigned long long wcw = ((unsigned long long)hi << 32) | lo;
        int gm = 0;
#pragma unroll
        for (int ntg = 0; ntg < 8; ntg++)
            if ((wcw >> (ntg * 8)) & 0xffull) gm |= 1 << ntg;
        if (gm == 0) continue;   // nothing allowed in this tile for this warp

        const uint32_t ksm = sb + AK_OFF + s * 16384;
        const uint32_t vsm = sb + AV_OFF + s * 16384;

        // ---- S = Q K^T (only active column groups) ----
        float sacc[8][4];
#pragma unroll
        for (int j = 0; j < 8; j++)
#pragma unroll
            for (int r = 0; r < 4; r++) sacc[j][r] = 0.f;
#pragma unroll
        for (int ks = 0; ks < 8; ks++) {
            const int c0 = ks * 2;
            uint32_t a0, a1, a2, a3;
            {
                int cc = c0 + a_ca;
                uint32_t addr = sb + AQ_OFF + (uint32_t)((cc >> 3) * 16384) + a_rp
                              + (uint32_t)((((uint32_t)(cc & 7)) ^ (uint32_t)l7) * 16);
                ldsm_x4(a0, a1, a2, a3, addr);
            }
            uint32_t bf[8][2];
#pragma unroll
            for (int pr = 0; pr < 4; pr++) {
                if (((gm >> (2 * pr)) & 3) == 0) continue;   // n-groups 2pr,2pr+1
                int cc = c0 + b_ca;
                uint32_t addr = ksm + (uint32_t)((cc >> 3) * 8192) + (uint32_t)(pr * 16 * 128)
                              + b_rp + (uint32_t)((((uint32_t)(cc & 7)) ^ (uint32_t)l7) * 16);
                ldsm_x4(bf[2 * pr][0], bf[2 * pr][1], bf[2 * pr + 1][0], bf[2 * pr + 1][1], addr);
            }
#pragma unroll
            for (int nt = 0; nt < 8; nt++)
                if ((gm >> nt) & 1)
                    mma_tf32(sacc[nt], a0, a1, a2, a3, bf[nt][0], bf[nt][1]);
        }

        // ---- mask + scale + online softmax (active groups only) ----
        float tm0 = -INFINITY, tm1 = -INFINITY;
#pragma unroll
        for (int nt = 0; nt < 8; nt++) {
            if (!((gm >> nt) & 1)) continue;
            int col = nt * 8 + 2 * t;
            sacc[nt][0] = ((w0 >> col) & 1ull) ? sacc[nt][0] * 0.125f : -1e9f;
            sacc[nt][1] = ((w0 >> (col + 1)) & 1ull) ? sacc[nt][1] * 0.125f : -1e9f;
            sacc[nt][2] = ((w1 >> col) & 1ull) ? sacc[nt][2] * 0.125f : -1e9f;
            sacc[nt][3] = ((w1 >> (col + 1)) & 1ull) ? sacc[nt][3] * 0.125f : -1e9f;
            tm0 = fmaxf(tm0, fmaxf(sacc[nt][0], sacc[nt][1]));
            tm1 = fmaxf(tm1, fmaxf(sacc[nt][2], sacc[nt][3]));
        }
#pragma unroll
        for (int o = 1; o <= 2; o <<= 1) {
            tm0 = fmaxf(tm0, __shfl_xor_sync(0xffffffffu, tm0, o));
            tm1 = fmaxf(tm1, __shfl_xor_sync(0xffffffffu, tm1, o));
        }
        float mn0 = fmaxf(m0, tm0), mn1 = fmaxf(m1, tm1);
        float al0 = __expf(m0 - mn0), al1 = __expf(m1 - mn1);
        m0 = mn0; m1 = mn1;
        float rs0 = 0.f, rs1 = 0.f;
#pragma unroll
        for (int nt = 0; nt < 8; nt++) {
            if (!((gm >> nt) & 1)) continue;   // PV reads group nt only if active
            float p0 = __expf(sacc[nt][0] - mn0);
            float p1 = __expf(sacc[nt][1] - mn0);
            float p2 = __expf(sacc[nt][2] - mn1);
            float p3 = __expf(sacc[nt][3] - mn1);
            rs0 += p0 + p1; rs1 += p2 + p3;
            int cp = nt * 8 + 2 * t;
            int cc = cp >> 2;
            uint32_t base = sb + AP_OFF + (uint32_t)((cc >> 3) * 16384)
                          + (uint32_t)((((uint32_t)(cc & 7)) ^ (uint32_t)g) * 16)
                          + (uint32_t)((cp & 3) * 4);
            sts64(base + (uint32_t)((wid * 16 + g) * 128), p0, p1);
            sts64(base + (uint32_t)((wid * 16 + g + 8) * 128), p2, p3);
        }
#pragma unroll
        for (int o = 1; o <= 2; o <<= 1) {
            rs0 += __shfl_xor_sync(0xffffffffu, rs0, o);
            rs1 += __shfl_xor_sync(0xffffffffu, rs1, o);
        }
        le0 = le0 * al0 + rs0;
        le1 = le1 * al1 + rs1;
#pragma unroll
        for (int nt = 0; nt < 8; nt++) {
            oacc[nt][0] *= al0; oacc[nt][1] *= al0;
            oacc[nt][2] *= al1; oacc[nt][3] *= al1;
        }
        __syncwarp(0xffffffffu);   // P rows are warp-private

        // ---- O += P V: k-step ks covers tokens [8ks,8ks+8) = group ks ----
#pragma unroll
        for (int ks = 0; ks < 8; ks++) {
            if (!((gm >> ks) & 1)) continue;
            const int c0 = ks * 2;
            uint32_t a0, a1, a2, a3;
            {
                int cc = c0 + a_ca;
                uint32_t addr = sb + AP_OFF + (uint32_t)((cc >> 3) * 16384) + a_rp
                              + (uint32_t)((((uint32_t)(cc & 7)) ^ (uint32_t)l7) * 16);
                ldsm_x4(a0, a1, a2, a3, addr);
            }
            uint32_t bf[8][2];
#pragma unroll
            for (int pr = 0; pr < 4; pr++) {
                int cc = c0 + b_ca;
                uint32_t addr = vsm + (uint32_t)((cc >> 3) * 8192) + (uint32_t)(pr * 16 * 128)
                              + b_rp + (uint32_t)((((uint32_t)(cc & 7)) ^ (uint32_t)l7) * 16);
                ldsm_x4(bf[2 * pr][0], bf[2 * pr][1], bf[2 * pr + 1][0], bf[2 * pr + 1][1], addr);
            }
#pragma unroll
            for (int nt = 0; nt < 8; nt++)
                mma_tf32(oacc[nt], a0, a1, a2, a3, bf[nt][0], bf[nt][1]);
        }
    }

    // ---- normalize + write ----
    float inv0 = 1.0f / le0, inv1 = 1.0f / le1;
    float* ob = O + (size_t)b * TT * DD + (size_t)h * HD;
#pragma unroll
    for (int nt = 0; nt < 8; nt++) {
        int col = nt * 8 + 2 * t;
        float2 o2;
        o2.x = oacc[nt][0] * inv0; o2.y = oacc[nt][1] * inv0;
        *(float2*)(ob + (size_t)rowq0 * DD + col) = o2;
        o2.x = oacc[nt][2] * inv1; o2.y = oacc[nt][3] * inv1;
        *(float2*)(ob + (size_t)(rowq0 + 8) * DD + col) = o2;
    }
}

// ---------------- launch ----------------
extern "C" void kernel_launch(void* const* d_in, const int* in_sizes, int n_in,
                              void* d_out, int out_size)
{
    (void)in_sizes; (void)n_in; (void)out_size;
    const float* x     = (const float*)d_in[0];
    const unsigned char* mask_raw = (const unsigned char*)d_in[1];
    const float* ln1_g = (const float*)d_in[2];
    const float* ln1_b = (const float*)d_in[3];
    const float* ln2_g = (const float*)d_in[4];
    const float* ln2_b = (const float*)d_in[5];
    const float* Wq    = (const float*)d_in[6];
    const float* Wk    = (const float*)d_in[7];
    const float* Wv    = (const float*)d_in[8];
    const float* Wo    = (const float*)d_in[9];
    const float* bo    = (const float*)d_in[10];
    const float* W1    = (const float*)d_in[11];
    const float* b1    = (const float*)d_in[12];
    const float* W2    = (const float*)d_in[13];
    const float* b2    = (const float*)d_in[14];
    float* out = (float*)d_out;

    float *h, *qkv, *vt, *attn, *xmid, *h2, *ff;
    float *wqkvt, *wot, *w1t, *w2t;
    unsigned long long* mbits;
    cudaGetSymbolAddress((void**)&h,     g_h);
    cudaGetSymbolAddress((void**)&qkv,   g_qkv);
    cudaGetSymbolAddress((void**)&vt,    g_vt);
    cudaGetSymbolAddress((void**)&attn,  g_attn);
    cudaGetSymbolAddress((void**)&xmid,  g_xmid);
    cudaGetSymbolAddress((void**)&h2,    g_h2);
    cudaGetSymbolAddress((void**)&ff,    g_ff);
    cudaGetSymbolAddress((void**)&wqkvt, g_wqkvt);
    cudaGetSymbolAddress((void**)&wot,   g_wot);
    cudaGetSymbolAddress((void**)&w1t,   g_w1t);
    cudaGetSymbolAddress((void**)&w2t,   g_w2t);
    cudaGetSymbolAddress((void**)&mbits, g_mask_bits);

    cudaFuncSetAttribute(attn_kernel, cudaFuncAttributeMaxDynamicSharedMemorySize, ATTN_SMEM);
    cudaFuncSetAttribute(mma_gemm<0>, cudaFuncAttributeMaxDynamicSharedMemorySize, GSMEM);
    cudaFuncSetAttribute(mma_gemm<2>, cudaFuncAttributeMaxDynamicSharedMemorySize, GSMEM);
    cudaFuncSetAttribute(mma_gemm<3>, cudaFuncAttributeMaxDynamicSharedMemorySize, GSMEM);

    // 0) fused prepass: LN1 + all weight transposes + mask bits (one launch)
    prepass_kernel<<<PRE_BLOCKS, 256>>>(x, ln1_g, ln1_b, Wq, Wk, Wv, Wo, W1, W2, mask_raw);
    // 1) fused QKV projection
    mma_gemm<0><<<dim3(QKVN / 128, ROWS / 128), 128, GSMEM>>>(h, wqkvt, nullptr, nullptr, qkv, ROWS, QKVN, DD);
    // 1b) V transpose per head
    vtrans_kernel<<<dim3(TT / 32, HD / 32, BB * HH), 256>>>(qkv, vt);
    // 2) attention (tensor core, sparsity-gated)
    attn_kernel<<<dim3(TT / 128, HH, BB), 256, ATTN_SMEM>>>(qkv, vt, mbits, attn);
    // 3) Wo + bias + residual(x)
    dim3 g1024(DD / 128, ROWS / 128);
    mma_gemm<2><<<g1024, 128, GSMEM>>>(attn, wot, bo, x, xmid, ROWS, DD, DD);
    // 4) LN2
    ln_kernel<<<ROWS, 256>>>(xmid, ln2_g, ln2_b, h2);
    // 5) FFN up + GELU
    mma_gemm<3><<<dim3(FF / 128, ROWS / 128), 128, GSMEM>>>(h2, w1t, b1, nullptr, ff, ROWS, FF, DD);
    // 6) FFN down + bias + residual(xmid) -> out
    mma_gemm<2><<<g1024, 128, GSMEM>>>(ff, w2t, b2, xmid, out, ROWS, DD, FF);
}